// round 9
// baseline (speedup 1.0000x reference)
#include <cuda_runtime.h>
#include <cuda_bf16.h>

#define HD 128
#define FD 16
#define SD 64
#define NB 8
#define NT 512
#define NCTA 128

typedef unsigned long long u64;

__device__ __align__(16) float4 g_W2p[65536]; // permuted W2, lane-coalesced for 512-thr layout
__device__ __align__(16) float4 g_W1p[4096];  // permuted W1, lane-coalesced

__device__ __forceinline__ u64 pk2(float lo, float hi) {
    u64 r; asm("mov.b64 %0,{%1,%2};" : "=l"(r) : "f"(lo), "f"(hi)); return r;
}
__device__ __forceinline__ void upk2(u64 v, float& lo, float& hi) {
    asm("mov.b64 {%0,%1},%2;" : "=f"(lo), "=f"(hi) : "l"(v));
}
__device__ __forceinline__ u64 f2fma(u64 a, u64 b, u64 c) {
    u64 d; asm("fma.rn.f32x2 %0,%1,%2,%3;" : "=l"(d) : "l"(a), "l"(b), "l"(c)); return d;
}

// One-shot gather-permute into lane-coalesced layouts.
// W2p[o], o = ((c*4+fi)*2+h)*512 + t  ->  W2row(t,fi)[c*8 + h*4 .. +3]
//   row(t,fi) = (t>>2)*16 + (t&3)*4 + fi      (c: 8-k chunk, h: k-half)
// W1p[o2], o2 = jc*128 + kx           ->  W1[kx][jc*4 .. +3]
__global__ void perm_kernel(const float* __restrict__ W1, const float* __restrict__ W2) {
    int o = blockIdx.x * 256 + threadIdx.x;
    if (o < 65536) {
        int t = o & 511, h = (o >> 9) & 1, fi = (o >> 10) & 3, c = o >> 12;
        int r = (t >> 2) * 16 + (t & 3) * 4 + fi;
        g_W2p[o] = ((const float4*)W2)[r * 32 + c * 2 + h];
    } else {
        int o2 = o - 65536;
        int jc = o2 >> 7, kx = o2 & 127;
        g_W1p[o2] = ((const float4*)W1)[kx * 32 + jc];
    }
}

__global__ void __launch_bounds__(NT, 1) cde_kernel(
    const float* __restrict__ x,   const float* __restrict__ W1,
    const float* __restrict__ b1v, const float* __restrict__ W2,
    const float* __restrict__ b2v, const float* __restrict__ Wi,
    const float* __restrict__ biv, float* __restrict__ out)
{
    __shared__ float sh_h [NB][HD];
    __shared__ float sh_hs[NB][HD];
    __shared__ __align__(16) float sh_zT[HD][NB];   // z transposed: k-major, 8 batches contiguous
    __shared__ float sh_kk[4][NB][HD];
    __shared__ __align__(16) u64 sh_dxp[FD][NB/2];  // dX packed batch-pairs
    __shared__ float sh_b1[HD];

    const int t   = threadIdx.x;
    const int gb0 = blockIdx.x * NB;

    if (t < HD) sh_b1[t] = b1v[t];

    // b2 registers: thread owns rows j*16 + fq*4 .. +3, j = t>>2, fq = t&3
    float b2r[4];
    {
        int j0 = (t >> 2) * 16 + (t & 3) * 4;
        #pragma unroll
        for (int fi = 0; fi < 4; fi++) b2r[fi] = b2v[j0 + fi];
    }

    // h0 = x[:,0] @ Wi^T + bi
    for (int it = t; it < NB * HD; it += NT) {
        int b = it >> 7, j = it & (HD - 1);
        const float* xr = x + (size_t)(gb0 + b) * (SD * FD);
        float acc = biv[j];
        #pragma unroll
        for (int f = 0; f < FD; f++) acc = fmaf(xr[f], Wi[j * FD + f], acc);
        sh_h[b][j] = acc;
    }
    __syncthreads();

    const float step = 1.0f / 63.0f;
    float r_segp = 0.0f, r_m0 = 0.0f, r_cc = 0.0f, r_dd = 0.0f;
    const int hb = t >> 4;   // hermite mapping (t < 128): batch 0..7
    const int hf = t & 15;   // feature

    #pragma unroll 1
    for (int i = 0; i < SD - 1; i++) {
        const float tA  = i * step;
        const float tB  = (i == SD - 2) ? 1.0f : (i + 1) * step;
        const float dti = tB - tA;

        // Hermite coeffs for this interval (threads 0..127, one (b,f) each)
        if (t < NB * FD) {
            const float* xr = x + ((size_t)(gb0 + hb) * SD + i) * FD + hf;
            float p0 = xr[0], p1 = xr[FD];
            float seg = (p1 - p0) / dti;
            float m0  = (i == 0) ? seg : r_segp;
            r_segp = seg;
            r_m0 = m0;
            r_cc = (3.0f * seg - (2.0f * m0 + seg)) / dti;
            r_dd = (-2.0f * seg + (m0 + seg)) / (dti * dti);
        }

        #pragma unroll 1
        for (int e = 0; e < 4; e++) {
            // dX for this eval, packed as batch-pairs
            if (t < NB * FD) {
                float fe = (e == 0) ? 0.0f
                         : (e == 1) ? dti * (1.0f / 3.0f)
                         : (e == 2) ? dti * (2.0f / 3.0f)
                         : dti;
                float dx = (e == 0) ? r_m0
                                    : fmaf(fmaf(3.0f * r_dd, fe, 2.0f * r_cc), fe, r_m0);
                float dxh = __shfl_down_sync(0xFFFFFFFFu, dx, 16);
                if ((t & 31) < 16) sh_dxp[hf][t >> 5] = pk2(dx, dxh);
            }
            // stage RK input hs
            for (int it = t; it < NB * HD; it += NT) {
                int b = it >> 7, j = it & (HD - 1);
                float hv = sh_h[b][j];
                if (e == 1)      hv = fmaf(dti * (1.0f / 3.0f), sh_kk[0][b][j], hv);
                else if (e == 2) hv = fmaf(dti, sh_kk[1][b][j] - sh_kk[0][b][j] * (1.0f / 3.0f), hv);
                else if (e == 3) hv = fmaf(dti, sh_kk[0][b][j] - sh_kk[1][b][j] + sh_kk[2][b][j], hv);
                sh_hs[b][j] = hv;
            }
            __syncthreads();

            // ---- phase A: z = tanh(hs @ W1^T + b1), thread=(kx, 2-batch group) ----
            {
                int kx = t & (HD - 1), grp = t >> 7, b0v = grp * 2;
                float a0 = sh_b1[kx], a1 = a0;
                #pragma unroll
                for (int jc = 0; jc < HD / 4; jc++) {
                    float4 w  = __ldg(&g_W1p[jc * HD + kx]);  // lane-coalesced
                    float4 hA = *(const float4*)&sh_hs[b0v + 0][jc * 4];
                    float4 hB = *(const float4*)&sh_hs[b0v + 1][jc * 4];
                    a0 = fmaf(w.x, hA.x, a0); a0 = fmaf(w.y, hA.y, a0);
                    a0 = fmaf(w.z, hA.z, a0); a0 = fmaf(w.w, hA.w, a0);
                    a1 = fmaf(w.x, hB.x, a1); a1 = fmaf(w.y, hB.y, a1);
                    a1 = fmaf(w.z, hB.z, a1); a1 = fmaf(w.w, hB.w, a1);
                }
                float2 zr;
                zr.x = tanhf(a0); zr.y = tanhf(a1);
                *(float2*)&sh_zT[kx][b0v] = zr;
            }
            __syncthreads();

            // ---- phase B: k_e[b][j] = sum_f dX[b][f]*(b2[jf] + W2[jf,:].z[b]) ----
            // 4 lanes per j (fq = t&3), each covering f = fq*4 .. fq*4+3
            {
                const int j  = t >> 2;
                const int fq = t & 3;

                u64 tot0 = 0, tot1 = 0, tot2 = 0, tot3 = 0;
                #pragma unroll 1
                for (int c = 0; c < 16; c++) {        // k-chunk of 8
                    u64 zp[8][4];
                    #pragma unroll
                    for (int kk = 0; kk < 8; kk++) {
                        ulonglong2 za = *(const ulonglong2*)&sh_zT[c * 8 + kk][0];
                        ulonglong2 zb = *(const ulonglong2*)&sh_zT[c * 8 + kk][4];
                        zp[kk][0] = za.x; zp[kk][1] = za.y;
                        zp[kk][2] = zb.x; zp[kk][3] = zb.y;
                    }
                    #pragma unroll
                    for (int fi = 0; fi < 4; fi++) {
                        // lane-coalesced permuted W2 reads (512 consecutive float4s per index)
                        float4 wa = __ldg(&g_W2p[((c * 4 + fi) * 2 + 0) * 512 + t]);
                        float4 wc = __ldg(&g_W2p[((c * 4 + fi) * 2 + 1) * 512 + t]);
                        u64 d0, d1, d2, d3;
                        if (c == 0) {
                            u64 bp = pk2(b2r[fi], b2r[fi]);
                            d0 = bp; d1 = bp; d2 = bp; d3 = bp;
                        } else {
                            d0 = 0; d1 = 0; d2 = 0; d3 = 0;
                        }
                        #define STEPK(wv, kk) { u64 wp = pk2(wv, wv); \
                            d0 = f2fma(wp, zp[kk][0], d0); d1 = f2fma(wp, zp[kk][1], d1); \
                            d2 = f2fma(wp, zp[kk][2], d2); d3 = f2fma(wp, zp[kk][3], d3); }
                        STEPK(wa.x, 0) STEPK(wa.y, 1) STEPK(wa.z, 2) STEPK(wa.w, 3)
                        STEPK(wc.x, 4) STEPK(wc.y, 5) STEPK(wc.z, 6) STEPK(wc.w, 7)
                        #undef STEPK
                        ulonglong2 qa = *(const ulonglong2*)&sh_dxp[fq * 4 + fi][0];
                        ulonglong2 qb = *(const ulonglong2*)&sh_dxp[fq * 4 + fi][2];
                        tot0 = f2fma(qa.x, d0, tot0); tot1 = f2fma(qa.y, d1, tot1);
                        tot2 = f2fma(qb.x, d2, tot2); tot3 = f2fma(qb.y, d3, tot3);
                    }
                }
                float tv[8];
                upk2(tot0, tv[0], tv[1]); upk2(tot1, tv[2], tv[3]);
                upk2(tot2, tv[4], tv[5]); upk2(tot3, tv[6], tv[7]);
                #pragma unroll
                for (int b = 0; b < 8; b++) {
                    tv[b] += __shfl_xor_sync(0xFFFFFFFFu, tv[b], 1);
                    tv[b] += __shfl_xor_sync(0xFFFFFFFFu, tv[b], 2);
                }
                if (fq == 0) {
                    #pragma unroll
                    for (int b = 0; b < 8; b++) sh_kk[e][b][j] = tv[b];
                }
            }
            __syncthreads();
        }

        // h += dt*(k1 + 3(k2+k3) + k4)/8
        for (int it = t; it < NB * HD; it += NT) {
            int b = it >> 7, j = it & (HD - 1);
            float k1 = sh_kk[0][b][j], k2 = sh_kk[1][b][j];
            float k3 = sh_kk[2][b][j], k4 = sh_kk[3][b][j];
            sh_h[b][j] = fmaf(dti * 0.125f, k1 + 3.0f * (k2 + k3) + k4, sh_h[b][j]);
        }
        __syncthreads();
    }

    for (int it = t; it < NB * HD; it += NT) {
        int b = it >> 7, j = it & (HD - 1);
        out[(size_t)(gb0 + b) * HD + j] = sh_h[b][j];
    }
}

extern "C" void kernel_launch(void* const* d_in, const int* in_sizes, int n_in,
                              void* d_out, int out_size) {
    const float* x   = (const float*)d_in[0];
    const float* W1  = (const float*)d_in[1];
    const float* b1  = (const float*)d_in[2];
    const float* W2  = (const float*)d_in[3];
    const float* b2  = (const float*)d_in[4];
    const float* Wi  = (const float*)d_in[5];
    const float* bi  = (const float*)d_in[6];
    float* out = (float*)d_out;
    perm_kernel<<<272, 256>>>(W1, W2);
    cde_kernel<<<NCTA, NT>>>(x, W1, b1, W2, b2, Wi, bi, out);
}

// round 10
// speedup vs baseline: 1.8293x; 1.8293x over previous
#include <cuda_runtime.h>
#include <cuda_bf16.h>

#define HD 128
#define FD 16
#define SD 64
#define NB 8
#define NT 256
#define NCTA 128

typedef unsigned long long u64;

__device__ __align__(16) float4 g_W2p[65536]; // permuted W2, lane-coalesced
__device__ __align__(16) float4 g_W1p[4096];  // permuted W1, lane-coalesced

__device__ __forceinline__ u64 pk2(float lo, float hi) {
    u64 r; asm("mov.b64 %0,{%1,%2};" : "=l"(r) : "f"(lo), "f"(hi)); return r;
}
__device__ __forceinline__ void upk2(u64 v, float& lo, float& hi) {
    asm("mov.b64 {%0,%1},%2;" : "=f"(lo), "=f"(hi) : "l"(v));
}
__device__ __forceinline__ u64 f2fma(u64 a, u64 b, u64 c) {
    u64 d; asm("fma.rn.f32x2 %0,%1,%2,%3;" : "=l"(d) : "l"(a), "l"(b), "l"(c)); return d;
}
__device__ __forceinline__ u64 f2add(u64 a, u64 b) {
    u64 d; asm("add.rn.f32x2 %0,%1,%2;" : "=l"(d) : "l"(a), "l"(b)); return d;
}

// One-shot gather-permute into lane-coalesced layouts (R4 256-thread layout).
// W2p[o], o = ((c*8+f)*2+h)*256 + t  ->  W2[row(t,f)][c*8+h*4 .. +3]
//   row(t,f) = (t>>1)*16 + (t&1)*8 + f
// W1p[o2], o2 = jc*128 + kx          ->  W1[kx][jc*4 .. +3]
__global__ void perm_kernel(const float* __restrict__ W1, const float* __restrict__ W2) {
    int o = blockIdx.x * 256 + threadIdx.x;
    if (o < 65536) {
        int t = o & 255, h = (o >> 8) & 1, f = (o >> 9) & 7, c = o >> 12;
        int r = (t >> 1) * 16 + (t & 1) * 8 + f;
        g_W2p[o] = ((const float4*)W2)[r * 32 + c * 2 + h];
    } else {
        int o2 = o - 65536;
        int jc = o2 >> 7, kx = o2 & 127;
        g_W1p[o2] = ((const float4*)W1)[kx * 32 + jc];
    }
}

__global__ void __launch_bounds__(NT, 1) cde_kernel(
    const float* __restrict__ x,   const float* __restrict__ W1,
    const float* __restrict__ b1v, const float* __restrict__ W2,
    const float* __restrict__ b2v, const float* __restrict__ Wi,
    const float* __restrict__ biv, float* __restrict__ out)
{
    __shared__ float sh_h [NB][HD];
    __shared__ float sh_hs[NB][HD];
    __shared__ __align__(16) float sh_zT[HD][NB];   // z transposed: k-major, 8 batches contiguous
    __shared__ float sh_kk[4][NB][HD];
    __shared__ __align__(16) u64 sh_dxp[FD][NB/2];  // dX packed batch-pairs
    __shared__ float sh_b1[HD];

    const int t   = threadIdx.x;
    const int gb0 = blockIdx.x * NB;

    if (t < HD) sh_b1[t] = b1v[t];

    // b2 registers: thread owns rows (t>>1)*16 + (t&1)*8 .. +7
    float b2r[8];
    {
        int j0 = (t >> 1) * 16 + (t & 1) * 8;
        #pragma unroll
        for (int f = 0; f < 8; f++) b2r[f] = b2v[j0 + f];
    }

    // h0 = x[:,0] @ Wi^T + bi
    for (int it = t; it < NB * HD; it += NT) {
        int b = it >> 7, j = it & (HD - 1);
        const float* xr = x + (size_t)(gb0 + b) * (SD * FD);
        float acc = biv[j];
        #pragma unroll
        for (int f = 0; f < FD; f++) acc = fmaf(xr[f], Wi[j * FD + f], acc);
        sh_h[b][j] = acc;
    }
    __syncthreads();

    const float step = 1.0f / 63.0f;
    float r_segp = 0.0f, r_m0 = 0.0f, r_cc = 0.0f, r_dd = 0.0f;
    const int hb = t >> 4;   // hermite mapping (t < 128): batch 0..7
    const int hf = t & 15;   // feature

    #pragma unroll 1
    for (int i = 0; i < SD - 1; i++) {
        const float tA  = i * step;
        const float tB  = (i == SD - 2) ? 1.0f : (i + 1) * step;
        const float dti = tB - tA;

        // Hermite coeffs for this interval (threads 0..127, one (b,f) each)
        if (t < NB * FD) {
            const float* xr = x + ((size_t)(gb0 + hb) * SD + i) * FD + hf;
            float p0 = xr[0], p1 = xr[FD];
            float seg = (p1 - p0) / dti;
            float m0  = (i == 0) ? seg : r_segp;
            r_segp = seg;
            r_m0 = m0;
            r_cc = (3.0f * seg - (2.0f * m0 + seg)) / dti;
            r_dd = (-2.0f * seg + (m0 + seg)) / (dti * dti);
        }

        #pragma unroll 1
        for (int e = 0; e < 4; e++) {
            // dX for this eval, packed as batch-pairs
            if (t < NB * FD) {
                float fe = (e == 0) ? 0.0f
                         : (e == 1) ? dti * (1.0f / 3.0f)
                         : (e == 2) ? dti * (2.0f / 3.0f)
                         : dti;
                float dx = (e == 0) ? r_m0
                                    : fmaf(fmaf(3.0f * r_dd, fe, 2.0f * r_cc), fe, r_m0);
                float dxh = __shfl_down_sync(0xFFFFFFFFu, dx, 16);
                if ((t & 31) < 16) sh_dxp[hf][t >> 5] = pk2(dx, dxh);
            }
            // stage RK input hs
            for (int it = t; it < NB * HD; it += NT) {
                int b = it >> 7, j = it & (HD - 1);
                float hv = sh_h[b][j];
                if (e == 1)      hv = fmaf(dti * (1.0f / 3.0f), sh_kk[0][b][j], hv);
                else if (e == 2) hv = fmaf(dti, sh_kk[1][b][j] - sh_kk[0][b][j] * (1.0f / 3.0f), hv);
                else if (e == 3) hv = fmaf(dti, sh_kk[0][b][j] - sh_kk[1][b][j] + sh_kk[2][b][j], hv);
                sh_hs[b][j] = hv;
            }
            __syncthreads();

            // ---- phase A: z = tanh(hs @ W1^T + b1), thread=(kx, 4-batch half) ----
            {
                int kx = t & (HD - 1), half = t >> 7, b0v = half * 4;
                float a0 = sh_b1[kx], a1 = a0, a2 = a0, a3 = a0;
                #pragma unroll
                for (int jc = 0; jc < HD / 4; jc++) {
                    float4 w  = __ldg(&g_W1p[jc * HD + kx]);  // lane-coalesced, L1-resident
                    float4 hA = *(const float4*)&sh_hs[b0v + 0][jc * 4];
                    float4 hB = *(const float4*)&sh_hs[b0v + 1][jc * 4];
                    float4 hC = *(const float4*)&sh_hs[b0v + 2][jc * 4];
                    float4 hE = *(const float4*)&sh_hs[b0v + 3][jc * 4];
                    a0 = fmaf(w.x, hA.x, a0); a0 = fmaf(w.y, hA.y, a0);
                    a0 = fmaf(w.z, hA.z, a0); a0 = fmaf(w.w, hA.w, a0);
                    a1 = fmaf(w.x, hB.x, a1); a1 = fmaf(w.y, hB.y, a1);
                    a1 = fmaf(w.z, hB.z, a1); a1 = fmaf(w.w, hB.w, a1);
                    a2 = fmaf(w.x, hC.x, a2); a2 = fmaf(w.y, hC.y, a2);
                    a2 = fmaf(w.z, hC.z, a2); a2 = fmaf(w.w, hC.w, a2);
                    a3 = fmaf(w.x, hE.x, a3); a3 = fmaf(w.y, hE.y, a3);
                    a3 = fmaf(w.z, hE.z, a3); a3 = fmaf(w.w, hE.w, a3);
                }
                float4 zr;
                zr.x = tanhf(a0); zr.y = tanhf(a1); zr.z = tanhf(a2); zr.w = tanhf(a3);
                *(float4*)&sh_zT[kx][b0v] = zr;
            }
            __syncthreads();

            // ---- phase B: software-pipelined W2 GEMV, per-f accumulators ----
            // k_e[b][j] = sum_f dX[b][f]*(b2[jf] + W2[jf,:].z[b]); dX applied at end.
            {
                const int fh = t & 1;

                u64 acc[8][4];
                #pragma unroll
                for (int f = 0; f < 8; f++) {
                    acc[f][0] = 0; acc[f][1] = 0; acc[f][2] = 0; acc[f][3] = 0;
                }

                // preload both halves of chunk 0
                float4 bufA[8], bufB[8];
                #pragma unroll
                for (int f = 0; f < 8; f++) bufA[f] = __ldcs(&g_W2p[(f * 2 + 0) * 256 + t]);
                #pragma unroll
                for (int f = 0; f < 8; f++) bufB[f] = __ldcs(&g_W2p[(f * 2 + 1) * 256 + t]);

                #pragma unroll 1
                for (int c = 0; c < 16; c++) {
                    const int cn = (c + 1 < 16) ? c + 1 : 15;  // redundant last prefetch

                    // zp for k = c*8 .. c*8+3
                    u64 zp[4][4];
                    #pragma unroll
                    for (int kk = 0; kk < 4; kk++) {
                        ulonglong2 za = *(const ulonglong2*)&sh_zT[c * 8 + kk][0];
                        ulonglong2 zb = *(const ulonglong2*)&sh_zT[c * 8 + kk][4];
                        zp[kk][0] = za.x; zp[kk][1] = za.y;
                        zp[kk][2] = zb.x; zp[kk][3] = zb.y;
                    }
                    #pragma unroll
                    for (int f = 0; f < 8; f++) {
                        float4 w = bufA[f];
                        bufA[f] = __ldcs(&g_W2p[((cn * 8 + f) * 2 + 0) * 256 + t]); // prefetch
                        #define STEPP(wv, kk) { u64 wp = pk2(wv, wv); \
                            acc[f][0] = f2fma(wp, zp[kk][0], acc[f][0]); \
                            acc[f][1] = f2fma(wp, zp[kk][1], acc[f][1]); \
                            acc[f][2] = f2fma(wp, zp[kk][2], acc[f][2]); \
                            acc[f][3] = f2fma(wp, zp[kk][3], acc[f][3]); }
                        STEPP(w.x, 0) STEPP(w.y, 1) STEPP(w.z, 2) STEPP(w.w, 3)
                    }

                    // zp for k = c*8+4 .. c*8+7
                    #pragma unroll
                    for (int kk = 0; kk < 4; kk++) {
                        ulonglong2 za = *(const ulonglong2*)&sh_zT[c * 8 + 4 + kk][0];
                        ulonglong2 zb = *(const ulonglong2*)&sh_zT[c * 8 + 4 + kk][4];
                        zp[kk][0] = za.x; zp[kk][1] = za.y;
                        zp[kk][2] = zb.x; zp[kk][3] = zb.y;
                    }
                    #pragma unroll
                    for (int f = 0; f < 8; f++) {
                        float4 w = bufB[f];
                        bufB[f] = __ldcs(&g_W2p[((cn * 8 + f) * 2 + 1) * 256 + t]); // prefetch
                        STEPP(w.x, 0) STEPP(w.y, 1) STEPP(w.z, 2) STEPP(w.w, 3)
                        #undef STEPP
                    }
                }

                // fold b2 and dX once at the end
                u64 tot0 = 0, tot1 = 0, tot2 = 0, tot3 = 0;
                #pragma unroll
                for (int f = 0; f < 8; f++) {
                    u64 bp = pk2(b2r[f], b2r[f]);
                    u64 s0 = f2add(acc[f][0], bp);
                    u64 s1 = f2add(acc[f][1], bp);
                    u64 s2 = f2add(acc[f][2], bp);
                    u64 s3 = f2add(acc[f][3], bp);
                    ulonglong2 qa = *(const ulonglong2*)&sh_dxp[fh * 8 + f][0];
                    ulonglong2 qb = *(const ulonglong2*)&sh_dxp[fh * 8 + f][2];
                    tot0 = f2fma(qa.x, s0, tot0); tot1 = f2fma(qa.y, s1, tot1);
                    tot2 = f2fma(qb.x, s2, tot2); tot3 = f2fma(qb.y, s3, tot3);
                }

                float tv[8];
                upk2(tot0, tv[0], tv[1]); upk2(tot1, tv[2], tv[3]);
                upk2(tot2, tv[4], tv[5]); upk2(tot3, tv[6], tv[7]);
                const int j = t >> 1;
                #pragma unroll
                for (int b = 0; b < 8; b++)
                    tv[b] += __shfl_xor_sync(0xFFFFFFFFu, tv[b], 1);
                if (fh == 0) {
                    #pragma unroll
                    for (int b = 0; b < 8; b++) sh_kk[e][b][j] = tv[b];
                }
            }
            __syncthreads();
        }

        // h += dt*(k1 + 3(k2+k3) + k4)/8
        for (int it = t; it < NB * HD; it += NT) {
            int b = it >> 7, j = it & (HD - 1);
            float k1 = sh_kk[0][b][j], k2 = sh_kk[1][b][j];
            float k3 = sh_kk[2][b][j], k4 = sh_kk[3][b][j];
            sh_h[b][j] = fmaf(dti * 0.125f, k1 + 3.0f * (k2 + k3) + k4, sh_h[b][j]);
        }
        __syncthreads();
    }

    for (int it = t; it < NB * HD; it += NT) {
        int b = it >> 7, j = it & (HD - 1);
        out[(size_t)(gb0 + b) * HD + j] = sh_h[b][j];
    }
}

extern "C" void kernel_launch(void* const* d_in, const int* in_sizes, int n_in,
                              void* d_out, int out_size) {
    const float* x   = (const float*)d_in[0];
    const float* W1  = (const float*)d_in[1];
    const float* b1  = (const float*)d_in[2];
    const float* W2  = (const float*)d_in[3];
    const float* b2  = (const float*)d_in[4];
    const float* Wi  = (const float*)d_in[5];
    const float* bi  = (const float*)d_in[6];
    float* out = (float*)d_out;
    perm_kernel<<<272, 256>>>(W1, W2);
    cde_kernel<<<NCTA, NT>>>(x, W1, b1, W2, b2, Wi, bi, out);
}

// round 13
// speedup vs baseline: 1.9161x; 1.0474x over previous
#include <cuda_runtime.h>
#include <cuda_bf16.h>

#define HD 128
#define FD 16
#define SD 64
#define NB 8
#define NT 256
#define NCTA 128

typedef unsigned long long u64;

__device__ __align__(16) float4 g_W2p[65536]; // permuted W2, lane-coalesced
__device__ __align__(16) float4 g_W1p[4096];  // permuted W1, lane-coalesced

__device__ __forceinline__ u64 pk2(float lo, float hi) {
    u64 r; asm("mov.b64 %0,{%1,%2};" : "=l"(r) : "f"(lo), "f"(hi)); return r;
}
__device__ __forceinline__ void upk2(u64 v, float& lo, float& hi) {
    asm("mov.b64 {%0,%1},%2;" : "=f"(lo), "=f"(hi) : "l"(v));
}
__device__ __forceinline__ u64 f2fma(u64 a, u64 b, u64 c) {
    u64 d; asm("fma.rn.f32x2 %0,%1,%2,%3;" : "=l"(d) : "l"(a), "l"(b), "l"(c)); return d;
}
__device__ __forceinline__ u64 f2add(u64 a, u64 b) {
    u64 d; asm("add.rn.f32x2 %0,%1,%2;" : "=l"(d) : "l"(a), "l"(b)); return d;
}

// One-shot gather-permute into lane-coalesced layouts (256-thread layout).
// W2p[o], o = ((c*8+f)*2+h)*256 + t  ->  W2[row(t,f)][c*8+h*4 .. +3]
//   row(t,f) = (t>>1)*16 + (t&1)*8 + f
// W1p[o2], o2 = jc*128 + kx          ->  W1[kx][jc*4 .. +3]
__global__ void perm_kernel(const float* __restrict__ W1, const float* __restrict__ W2) {
    int o = blockIdx.x * 256 + threadIdx.x;
    if (o < 65536) {
        int t = o & 255, h = (o >> 8) & 1, f = (o >> 9) & 7, c = o >> 12;
        int r = (t >> 1) * 16 + (t & 1) * 8 + f;
        g_W2p[o] = ((const float4*)W2)[r * 32 + c * 2 + h];
    } else {
        int o2 = o - 65536;
        int jc = o2 >> 7, kx = o2 & 127;
        g_W1p[o2] = ((const float4*)W1)[kx * 32 + jc];
    }
}

__global__ void __launch_bounds__(NT, 1) cde_kernel(
    const float* __restrict__ x,   const float* __restrict__ W1,
    const float* __restrict__ b1v, const float* __restrict__ W2,
    const float* __restrict__ b2v, const float* __restrict__ Wi,
    const float* __restrict__ biv, float* __restrict__ out)
{
    __shared__ float sh_h [NB][HD];
    __shared__ __align__(16) float sh_hsT[HD][NB];  // hs transposed: j-major, batches contiguous
    __shared__ __align__(16) float sh_zT[HD][NB];   // z transposed: k-major, batches contiguous
    __shared__ float sh_kk[4][NB][HD];
    __shared__ __align__(16) u64 sh_dxp4[4][FD][NB/2]; // dX per eval, packed batch-pairs
    __shared__ float sh_b1[HD];

    const int t   = threadIdx.x;
    const int gb0 = blockIdx.x * NB;

    if (t < HD) sh_b1[t] = b1v[t];

    // b2 registers: thread owns rows (t>>1)*16 + (t&1)*8 .. +7
    float b2r[8];
    {
        int j0 = (t >> 1) * 16 + (t & 1) * 8;
        #pragma unroll
        for (int f = 0; f < 8; f++) b2r[f] = b2v[j0 + f];
    }

    // h0 = x[:,0] @ Wi^T + bi
    for (int it = t; it < NB * HD; it += NT) {
        int b = it >> 7, j = it & (HD - 1);
        const float* xr = x + (size_t)(gb0 + b) * (SD * FD);
        float acc = biv[j];
        #pragma unroll
        for (int f = 0; f < FD; f++) acc = fmaf(xr[f], Wi[j * FD + f], acc);
        sh_h[b][j] = acc;
    }
    __syncthreads();

    const float step = 1.0f / 63.0f;
    float r_segp = 0.0f;
    const int hb = t >> 4;   // hermite mapping (t < 128): batch 0..7
    const int hf = t & 15;   // feature

    #pragma unroll 1
    for (int i = 0; i < SD - 1; i++) {
        const float tA  = i * step;
        const float tB  = (i == SD - 2) ? 1.0f : (i + 1) * step;
        const float dti = tB - tA;

        // Hermite coeffs + all 4 evals' dX for this interval (threads 0..127)
        if (t < NB * FD) {
            const float* xr = x + ((size_t)(gb0 + hb) * SD + i) * FD + hf;
            float p0 = xr[0], p1 = xr[FD];
            float seg = (p1 - p0) / dti;
            float m0  = (i == 0) ? seg : r_segp;
            r_segp = seg;
            float cc = (3.0f * seg - (2.0f * m0 + seg)) / dti;
            float dd = (-2.0f * seg + (m0 + seg)) / (dti * dti);
            #pragma unroll
            for (int e = 0; e < 4; e++) {
                float fe = (e == 0) ? 0.0f
                         : (e == 1) ? dti * (1.0f / 3.0f)
                         : (e == 2) ? dti * (2.0f / 3.0f)
                         : dti;
                float dx = (e == 0) ? m0
                                    : fmaf(fmaf(3.0f * dd, fe, 2.0f * cc), fe, m0);
                float dxh = __shfl_down_sync(0xFFFFFFFFu, dx, 16);
                if ((t & 31) < 16) sh_dxp4[e][hf][t >> 5] = pk2(dx, dxh);
            }
        }

        #pragma unroll 1
        for (int e = 0; e < 4; e++) {
            // stage RK input hs (transposed: j-major, batch contiguous)
            for (int it = t; it < NB * HD; it += NT) {
                int b = it >> 7, j = it & (HD - 1);
                float hv = sh_h[b][j];
                if (e == 1)      hv = fmaf(dti * (1.0f / 3.0f), sh_kk[0][b][j], hv);
                else if (e == 2) hv = fmaf(dti, sh_kk[1][b][j] - sh_kk[0][b][j] * (1.0f / 3.0f), hv);
                else if (e == 3) hv = fmaf(dti, sh_kk[0][b][j] - sh_kk[1][b][j] + sh_kk[2][b][j], hv);
                sh_hsT[j][b] = hv;
            }
            __syncthreads();

            // ---- phase A: z = tanh(hs @ W1^T + b1), f32x2 over batch-pairs ----
            {
                int kx = t & (HD - 1), half = t >> 7, b0v = half * 4;
                u64 bp = pk2(sh_b1[kx], sh_b1[kx]);
                u64 a01 = bp, a23 = bp;
                #pragma unroll
                for (int jc = 0; jc < HD / 4; jc++) {
                    float4 w = __ldg(&g_W1p[jc * HD + kx]);  // lane-coalesced, L1-resident
                    #define ASTEP(wv, jj) { \
                        ulonglong2 hp = *(const ulonglong2*)&sh_hsT[jc * 4 + jj][b0v]; \
                        u64 wp = pk2(wv, wv); \
                        a01 = f2fma(wp, hp.x, a01); \
                        a23 = f2fma(wp, hp.y, a23); }
                    ASTEP(w.x, 0) ASTEP(w.y, 1) ASTEP(w.z, 2) ASTEP(w.w, 3)
                    #undef ASTEP
                }
                float v0, v1, v2, v3;
                upk2(a01, v0, v1); upk2(a23, v2, v3);
                float4 zr;
                zr.x = tanhf(v0); zr.y = tanhf(v1); zr.z = tanhf(v2); zr.w = tanhf(v3);
                *(float4*)&sh_zT[kx][b0v] = zr;
            }
            __syncthreads();

            // ---- phase B: software-pipelined W2 GEMV, per-f accumulators ----
            {
                const int fh = t & 1;

                u64 acc[8][4];
                #pragma unroll
                for (int f = 0; f < 8; f++) {
                    acc[f][0] = 0; acc[f][1] = 0; acc[f][2] = 0; acc[f][3] = 0;
                }

                // preload both halves of chunk 0
                float4 bufA[8], bufB[8];
                #pragma unroll
                for (int f = 0; f < 8; f++) bufA[f] = __ldcs(&g_W2p[(f * 2 + 0) * 256 + t]);
                #pragma unroll
                for (int f = 0; f < 8; f++) bufB[f] = __ldcs(&g_W2p[(f * 2 + 1) * 256 + t]);

                #pragma unroll 1
                for (int c = 0; c < 16; c++) {
                    const int cn = (c + 1 < 16) ? c + 1 : 15;  // redundant last prefetch

                    // zp for k = c*8 .. c*8+3 (uniform-address broadcast LDS)
                    u64 zp[4][4];
                    #pragma unroll
                    for (int kk = 0; kk < 4; kk++) {
                        ulonglong2 za = *(const ulonglong2*)&sh_zT[c * 8 + kk][0];
                        ulonglong2 zb = *(const ulonglong2*)&sh_zT[c * 8 + kk][4];
                        zp[kk][0] = za.x; zp[kk][1] = za.y;
                        zp[kk][2] = zb.x; zp[kk][3] = zb.y;
                    }
                    #pragma unroll
                    for (int f = 0; f < 8; f++) {
                        float4 w = bufA[f];
                        bufA[f] = __ldcs(&g_W2p[((cn * 8 + f) * 2 + 0) * 256 + t]); // prefetch
                        #define STEPP(wv, kk) { u64 wp = pk2(wv, wv); \
                            acc[f][0] = f2fma(wp, zp[kk][0], acc[f][0]); \
                            acc[f][1] = f2fma(wp, zp[kk][1], acc[f][1]); \
                            acc[f][2] = f2fma(wp, zp[kk][2], acc[f][2]); \
                            acc[f][3] = f2fma(wp, zp[kk][3], acc[f][3]); }
                        STEPP(w.x, 0) STEPP(w.y, 1) STEPP(w.z, 2) STEPP(w.w, 3)
                    }

                    // zp for k = c*8+4 .. c*8+7
                    #pragma unroll
                    for (int kk = 0; kk < 4; kk++) {
                        ulonglong2 za = *(const ulonglong2*)&sh_zT[c * 8 + 4 + kk][0];
                        ulonglong2 zb = *(const ulonglong2*)&sh_zT[c * 8 + 4 + kk][4];
                        zp[kk][0] = za.x; zp[kk][1] = za.y;
                        zp[kk][2] = zb.x; zp[kk][3] = zb.y;
                    }
                    #pragma unroll
                    for (int f = 0; f < 8; f++) {
                        float4 w = bufB[f];
                        bufB[f] = __ldcs(&g_W2p[((cn * 8 + f) * 2 + 1) * 256 + t]); // prefetch
                        STEPP(w.x, 0) STEPP(w.y, 1) STEPP(w.z, 2) STEPP(w.w, 3)
                        #undef STEPP
                    }
                }

                // fold b2 and dX once at the end
                u64 tot0 = 0, tot1 = 0, tot2 = 0, tot3 = 0;
                #pragma unroll
                for (int f = 0; f < 8; f++) {
                    u64 bp = pk2(b2r[f], b2r[f]);
                    u64 s0 = f2add(acc[f][0], bp);
                    u64 s1 = f2add(acc[f][1], bp);
                    u64 s2 = f2add(acc[f][2], bp);
                    u64 s3 = f2add(acc[f][3], bp);
                    ulonglong2 qa = *(const ulonglong2*)&sh_dxp4[e][fh * 8 + f][0];
                    ulonglong2 qb = *(const ulonglong2*)&sh_dxp4[e][fh * 8 + f][2];
                    tot0 = f2fma(qa.x, s0, tot0); tot1 = f2fma(qa.y, s1, tot1);
                    tot2 = f2fma(qb.x, s2, tot2); tot3 = f2fma(qb.y, s3, tot3);
                }

                float tv[8];
                upk2(tot0, tv[0], tv[1]); upk2(tot1, tv[2], tv[3]);
                upk2(tot2, tv[4], tv[5]); upk2(tot3, tv[6], tv[7]);
                const int j = t >> 1;
                #pragma unroll
                for (int b = 0; b < 8; b++)
                    tv[b] += __shfl_xor_sync(0xFFFFFFFFu, tv[b], 1);
                if (fh == 0) {
                    #pragma unroll
                    for (int b = 0; b < 8; b++) sh_kk[e][b][j] = tv[b];
                }
            }
            __syncthreads();
        }

        // h += dt*(k1 + 3(k2+k3) + k4)/8
        for (int it = t; it < NB * HD; it += NT) {
            int b = it >> 7, j = it & (HD - 1);
            float k1 = sh_kk[0][b][j], k2 = sh_kk[1][b][j];
            float k3 = sh_kk[2][b][j], k4 = sh_kk[3][b][j];
            sh_h[b][j] = fmaf(dti * 0.125f, k1 + 3.0f * (k2 + k3) + k4, sh_h[b][j]);
        }
        __syncthreads();
    }

    for (int it = t; it < NB * HD; it += NT) {
        int b = it >> 7, j = it & (HD - 1);
        out[(size_t)(gb0 + b) * HD + j] = sh_h[b][j];
    }
}

extern "C" void kernel_launch(void* const* d_in, const int* in_sizes, int n_in,
                              void* d_out, int out_size) {
    const float* x   = (const float*)d_in[0];
    const float* W1  = (const float*)d_in[1];
    const float* b1  = (const float*)d_in[2];
    const float* W2  = (const float*)d_in[3];
    const float* b2  = (const float*)d_in[4];
    const float* Wi  = (const float*)d_in[5];
    const float* bi  = (const float*)d_in[6];
    float* out = (float*)d_out;
    perm_kernel<<<272, 256>>>(W1, W2);
    cde_kernel<<<NCTA, NT>>>(x, W1, b1, W2, b2, Wi, bi, out);
}